// round 7
// baseline (speedup 1.0000x reference)
#include <cuda_runtime.h>
#include <math.h>
#include <stdint.h>

#define N_USERS   100000
#define N_RECIPES 50000
#define NE        600000
#define NL        200000
#define HDIM      128
#define OUTDIM    64

// ---------------- scratch (no allocation allowed) ----------------
__device__ __align__(128) float g_hu[(size_t)N_USERS * HDIM];
__device__ __align__(128) float g_hr[(size_t)N_RECIPES * HDIM];
__device__ __align__(128) float g_mean_r[(size_t)N_RECIPES * HDIM];
__device__ __align__(128) float g_mean_u[(size_t)N_USERS * HDIM];
__device__ __align__(128) float g_r1[(size_t)N_RECIPES * HDIM];
__device__ __align__(128) float g_u1[(size_t)N_USERS * HDIM];
__device__ __align__(128) float g_mr2[(size_t)N_RECIPES * HDIM];
__device__ __align__(128) float g_mu2[(size_t)N_USERS * HDIM];
__device__ __align__(128) float g_zr[(size_t)N_RECIPES * OUTDIM];
__device__ __align__(128) float g_zu[(size_t)N_USERS * OUTDIM];

__device__ __align__(128) int g_off_r[N_RECIPES + 1];
__device__ __align__(128) int g_off_u[N_USERS + 1];
__device__ __align__(128) int g_cur_r[N_RECIPES];
__device__ __align__(128) int g_cur_u[N_USERS];
__device__ __align__(128) int g_adj_r[NE];
__device__ __align__(128) int g_adj_u[NE];
__device__ __align__(128) int g_bsum_r[64];
__device__ __align__(128) int g_bsum_u[128];

// pre-rounded + k-permuted tf32 weights and inputs
#define W_TOTAL 147456
#define XU_ELEMS (N_USERS * HDIM)      // 12,800,000
#define XR_ELEMS (N_RECIPES * 256)    // 12,800,000
__device__ __align__(128) float g_wts[W_TOTAL];
__device__ __align__(128) float g_xu[XU_ELEMS];
__device__ __align__(128) float g_xr[XR_ELEMS];

// ---------------- helpers ----------------
__device__ __forceinline__ float f2tf32(float f) {
    uint32_t r;
    asm("cvt.rna.tf32.f32 %0, %1;" : "=r"(r) : "f"(f));
    return __uint_as_float(r);
}

__device__ __forceinline__ void mma_tf32(float* d,
                                         uint32_t a0, uint32_t a1, uint32_t a2, uint32_t a3,
                                         uint32_t b0, uint32_t b1) {
    asm volatile(
        "mma.sync.aligned.m16n8k8.row.col.f32.tf32.tf32.f32 "
        "{%0,%1,%2,%3}, {%4,%5,%6,%7}, {%8,%9}, {%0,%1,%2,%3};"
        : "+f"(d[0]), "+f"(d[1]), "+f"(d[2]), "+f"(d[3])
        : "r"(a0), "r"(a1), "r"(a2), "r"(a3), "r"(b0), "r"(b1));
}

__device__ __forceinline__ void cp_async16(uint32_t smem_dst, const void* gsrc) {
    asm volatile("cp.async.ca.shared.global [%0], [%1], 16;"
                 :: "r"(smem_dst), "l"(gsrc) : "memory");
}

// permute within each 32-k chunk: k' = (k%4)*8 + k/4  (all arrays have K%32==0,
// so dest = (i & ~31) + perm(i & 31) works on flat indices)
__device__ __forceinline__ int perm32(int kk) { return (kk & 3) * 8 + (kk >> 2); }

// ---------------- prep: round to tf32 + permute (weights + x inputs) ----------------
__global__ void prep_all(const float* __restrict__ w0, const float* __restrict__ w1,
                         const float* __restrict__ w2, const float* __restrict__ w3,
                         const float* __restrict__ w4, const float* __restrict__ w5,
                         const float* __restrict__ w6, const float* __restrict__ w7,
                         const float* __restrict__ w8, const float* __restrict__ w9,
                         const float* __restrict__ xu, const float* __restrict__ xr,
                         float* __restrict__ wts, float* __restrict__ xup,
                         float* __restrict__ xrp) {
    int i = blockIdx.x * blockDim.x + threadIdx.x;
    const float* src; float* dst; int li;
    if (i < W_TOTAL) {
        const float* s; int off;
        if      (i <  16384) { s = w0; off = 0;      }
        else if (i <  49152) { s = w1; off = 16384;  }
        else if (i <  65536) { s = w2; off = 49152;  }
        else if (i <  81920) { s = w3; off = 65536;  }
        else if (i <  98304) { s = w4; off = 81920;  }
        else if (i < 114688) { s = w5; off = 98304;  }
        else if (i < 122880) { s = w6; off = 114688; }
        else if (i < 131072) { s = w7; off = 122880; }
        else if (i < 139264) { s = w8; off = 131072; }
        else                 { s = w9; off = 139264; }
        float v = s[i - off];
        wts[(i & ~31) + perm32(i & 31)] = f2tf32(v);
        return;
    }
    i -= W_TOTAL;
    if (i < XU_ELEMS) { src = xu; dst = xup; li = i; }
    else {
        i -= XU_ELEMS;
        if (i >= XR_ELEMS) return;
        src = xr; dst = xrp; li = i;
    }
    dst[(li & ~31) + perm32(li & 31)] = f2tf32(src[li]);
}

// ---------------- two-sided tf32 GEMM, permuted tiles, all-cp.async ----------------
// out[n, J(@ldo)] = A[n,*] @ WA^T (+ B @ WB^T) + bias (+relu) (+round)
// All of A, B, WA, WB are pre-rounded tf32 in k-permuted layout; shared ld.
struct GSide {
    const float *A, *WA, *B, *WB, *bias;
    float *out;
    int n, ld, nch, cha, ldo;
};

template <int J, bool RELU, bool ROUND>
__global__ __launch_bounds__(256, 2)
void gemm_mma(GSide s0, GSide s1, int split) {
    constexpr int LDS = 36;
    constexpr int NT  = J / 16;      // 8 (J=128) or 4 (J=64)
    constexpr int WI  = J / 32;      // cp.async iters for W

    extern __shared__ float sm[];
    float* AsB = sm;                        // [2][128][LDS]
    float* WsB = sm + 2 * 128 * LDS;        // [2][J][LDS]

    const bool second = ((int)blockIdx.x >= split);
    const GSide s = second ? s1 : s0;
    const int row0 = (second ? (int)blockIdx.x - split : (int)blockIdx.x) * 128;

    const int tid  = threadIdx.x;
    const int lane = tid & 31;
    const int wid  = tid >> 5;
    const int wm   = wid & 3;
    const int wn   = wid >> 2;
    const int qr   = lane >> 2;
    const int qc   = lane & 3;

    float acc[2][NT][4];
    #pragma unroll
    for (int mt = 0; mt < 2; mt++)
        #pragma unroll
        for (int nt = 0; nt < NT; nt++)
            #pragma unroll
            for (int q = 0; q < 4; q++) acc[mt][nt][q] = 0.f;

    auto prefetch = [&](int c, int b) {
        const float* src; const float* w; int k0;
        if (c < s.cha) { src = s.A; w = s.WA; k0 = c * 32; }
        else           { src = s.B; w = s.WB; k0 = (c - s.cha) * 32; }
        const int ld = s.ld;
        uint32_t abase = (uint32_t)__cvta_generic_to_shared(AsB + b * 128 * LDS);
        #pragma unroll
        for (int i = 0; i < 4; i++) {
            int lin = tid + i * 256;
            int r = lin >> 3, qk = lin & 7;
            int gr = row0 + r;
            if (gr >= s.n) gr = s.n - 1;   // clamp: masked at epilogue
            cp_async16(abase + (uint32_t)(r * LDS + qk * 4) * 4,
                       &src[(size_t)gr * ld + k0 + qk * 4]);
        }
        uint32_t wbase = (uint32_t)__cvta_generic_to_shared(WsB + b * J * LDS);
        #pragma unroll
        for (int i = 0; i < WI; i++) {
            int lin = tid + i * 256;
            int j = lin >> 3, qk = lin & 7;
            cp_async16(wbase + (uint32_t)(j * LDS + qk * 4) * 4,
                       &w[(size_t)j * ld + k0 + qk * 4]);
        }
        asm volatile("cp.async.commit_group;" ::: "memory");
    };

    prefetch(0, 0);
    asm volatile("cp.async.wait_group 0;" ::: "memory");
    __syncthreads();

    const int nch = s.nch;
    for (int c = 0; c < nch; ++c) {
        const int b = c & 1;
        if (c + 1 < nch) prefetch(c + 1, b ^ 1);

        const float* as = AsB + b * 128 * LDS + (wm * 32) * LDS + qc * 8;
        const float* ws = WsB + b * J * LDS + (wn * NT * 8) * LDS + qc * 8;

        #pragma unroll
        for (int h = 0; h < 2; h++) {       // halves: ks(0,1) then ks(2,3)
            float4 av[4];
            #pragma unroll
            for (int mt = 0; mt < 2; mt++) {
                av[2 * mt]     = *reinterpret_cast<const float4*>(&as[(mt * 16 + qr) * LDS + h * 4]);
                av[2 * mt + 1] = *reinterpret_cast<const float4*>(&as[(mt * 16 + 8 + qr) * LDS + h * 4]);
            }
            #pragma unroll
            for (int g = 0; g < NT / 4; g++) {
                float4 bv[4];
                #pragma unroll
                for (int t = 0; t < 4; t++)
                    bv[t] = *reinterpret_cast<const float4*>(&ws[((g * 4 + t) * 8 + qr) * LDS + h * 4]);
                #pragma unroll
                for (int kk = 0; kk < 2; kk++) {
                    #pragma unroll
                    for (int mt = 0; mt < 2; mt++) {
                        const float* a0p = reinterpret_cast<const float*>(&av[2 * mt]);
                        const float* a1p = reinterpret_cast<const float*>(&av[2 * mt + 1]);
                        #pragma unroll
                        for (int t = 0; t < 4; t++) {
                            const float* bp = reinterpret_cast<const float*>(&bv[t]);
                            mma_tf32(acc[mt][g * 4 + t],
                                     __float_as_uint(a0p[2 * kk]),
                                     __float_as_uint(a1p[2 * kk]),
                                     __float_as_uint(a0p[2 * kk + 1]),
                                     __float_as_uint(a1p[2 * kk + 1]),
                                     __float_as_uint(bp[2 * kk]),
                                     __float_as_uint(bp[2 * kk + 1]));
                        }
                    }
                }
            }
        }

        if (c + 1 < nch) {
            asm volatile("cp.async.wait_group 0;" ::: "memory");
            __syncthreads();
        }
    }

    // epilogue: write to k-permuted output columns (next layer reads permuted)
    #pragma unroll
    for (int mt = 0; mt < 2; mt++) {
        #pragma unroll
        for (int nt = 0; nt < NT; nt++) {
            int gcol = wn * NT * 8 + nt * 8 + 2 * qc;
            float bx = __ldg(&s.bias[gcol]), by = __ldg(&s.bias[gcol + 1]);
            int r0 = row0 + wm * 32 + mt * 16 + qr;
            float v0 = acc[mt][nt][0] + bx, v1 = acc[mt][nt][1] + by;
            float v2 = acc[mt][nt][2] + bx, v3 = acc[mt][nt][3] + by;
            if (RELU) {
                v0 = fmaxf(v0, 0.f); v1 = fmaxf(v1, 0.f);
                v2 = fmaxf(v2, 0.f); v3 = fmaxf(v3, 0.f);
            }
            if (ROUND) {
                v0 = f2tf32(v0); v1 = f2tf32(v1);
                v2 = f2tf32(v2); v3 = f2tf32(v3);
            }
            int cb = gcol & ~31, lc = gcol & 31;
            int p0 = cb + perm32(lc);
            int p1 = cb + perm32(lc + 1);
            if (r0 < s.n) {
                s.out[(size_t)r0 * s.ldo + p0] = v0;
                s.out[(size_t)r0 * s.ldo + p1] = v1;
            }
            if (r0 + 8 < s.n) {
                s.out[(size_t)(r0 + 8) * s.ldo + p0] = v2;
                s.out[(size_t)(r0 + 8) * s.ldo + p1] = v3;
            }
        }
    }
}

// ---------------- merged small utility kernels ----------------
__global__ void zero_int2(int* __restrict__ p0, int n0, int* __restrict__ p1, int n1) {
    int i = blockIdx.x * blockDim.x + threadIdx.x;
    if (i < n0) p0[i] = 0;
    else if (i < n0 + n1) p1[i - n0] = 0;
}

__global__ void copy_int2(int* __restrict__ d0, const int* __restrict__ s0, int n0,
                          int* __restrict__ d1, const int* __restrict__ s1, int n1) {
    int i = blockIdx.x * blockDim.x + threadIdx.x;
    if (i < n0) d0[i] = s0[i];
    else if (i < n0 + n1) d1[i - n0] = s1[i - n0];
}

__global__ void count_deg(const int* __restrict__ es, const int* __restrict__ ed,
                          int* __restrict__ deg_u, int* __restrict__ deg_r, int E) {
    int e = blockIdx.x * blockDim.x + threadIdx.x;
    if (e < E) {
        atomicAdd(&deg_u[es[e]], 1);
        atomicAdd(&deg_r[ed[e]], 1);
    }
}

__global__ void scan_chunks2(const int* __restrict__ dg0, int* __restrict__ of0,
                             int* __restrict__ bs0, int n0, int nb0,
                             const int* __restrict__ dg1, int* __restrict__ of1,
                             int* __restrict__ bs1, int n1) {
    const int* deg; int* off; int* bsum; int n, lb;
    if ((int)blockIdx.x < nb0) { deg = dg0; off = of0; bsum = bs0; n = n0; lb = blockIdx.x; }
    else { deg = dg1; off = of1; bsum = bs1; n = n1; lb = blockIdx.x - nb0; }
    __shared__ int sh[1024];
    int t = threadIdx.x;
    int gid = lb * 1024 + t;
    int v = (gid < n) ? deg[gid] : 0;
    sh[t] = v;
    __syncthreads();
    #pragma unroll
    for (int d = 1; d < 1024; d <<= 1) {
        int add = (t >= d) ? sh[t - d] : 0;
        __syncthreads();
        sh[t] += add;
        __syncthreads();
    }
    if (gid < n) off[gid + 1] = sh[t];
    if (t == 1023) bsum[lb] = sh[1023];
    if (gid == 0) off[0] = 0;
}

__global__ void scan_bsums2(int* __restrict__ b0, int nb0, int* __restrict__ b1, int nb1) {
    if (threadIdx.x != 0) return;
    int* b = (blockIdx.x == 0) ? b0 : b1;
    int nb = (blockIdx.x == 0) ? nb0 : nb1;
    int acc = 0;
    for (int i = 0; i < nb; i++) { int t = b[i]; b[i] = acc; acc += t; }
}

__global__ void add_bsums2(int* __restrict__ of0, const int* __restrict__ bs0, int n0, int nb0,
                           int* __restrict__ of1, const int* __restrict__ bs1, int n1) {
    int* off; const int* bsum; int n, lb;
    if ((int)blockIdx.x < nb0) { off = of0; bsum = bs0; n = n0; lb = blockIdx.x; }
    else { off = of1; bsum = bs1; n = n1; lb = blockIdx.x - nb0; }
    int gid = lb * 1024 + threadIdx.x;
    if (gid < n) off[gid + 1] += bsum[lb];
}

__global__ void fill_adj(const int* __restrict__ es, const int* __restrict__ ed,
                         int* __restrict__ cur_u, int* __restrict__ cur_r,
                         int* __restrict__ adj_u, int* __restrict__ adj_r, int E) {
    int e = blockIdx.x * blockDim.x + threadIdx.x;
    if (e < E) {
        int s = es[e], d = ed[e];
        adj_r[atomicAdd(&cur_r[d], 1)] = s;
        adj_u[atomicAdd(&cur_u[s], 1)] = d;
    }
}

// ---------------- merged scatter-mean, 4-way unrolled, tf32-rounded out ----------------
__global__ void aggregate_mean2(
    const float* __restrict__ f0, const int* __restrict__ o0,
    const int* __restrict__ a0, float* __restrict__ out0, int n0,
    const float* __restrict__ f1, const int* __restrict__ o1,
    const int* __restrict__ a1, float* __restrict__ out1, int n1) {
    int w = (blockIdx.x * blockDim.x + threadIdx.x) >> 5;
    const float* feat; const int* off; const int* adj; float* out;
    if (w < n0) { feat = f0; off = o0; adj = a0; out = out0; }
    else {
        w -= n0;
        if (w >= n1) return;
        feat = f1; off = o1; adj = a1; out = out1;
    }
    int lane = threadIdx.x & 31;
    int s = off[w], e = off[w + 1];
    float4 acc = make_float4(0.f, 0.f, 0.f, 0.f);
    int i = s;
    for (; i + 4 <= e; i += 4) {
        int nb0 = __ldg(&adj[i]);
        int nb1 = __ldg(&adj[i + 1]);
        int nb2 = __ldg(&adj[i + 2]);
        int nb3 = __ldg(&adj[i + 3]);
        float4 v0 = *reinterpret_cast<const float4*>(&feat[(size_t)nb0 * HDIM + lane * 4]);
        float4 v1 = *reinterpret_cast<const float4*>(&feat[(size_t)nb1 * HDIM + lane * 4]);
        float4 v2 = *reinterpret_cast<const float4*>(&feat[(size_t)nb2 * HDIM + lane * 4]);
        float4 v3 = *reinterpret_cast<const float4*>(&feat[(size_t)nb3 * HDIM + lane * 4]);
        acc.x += v0.x + v1.x + v2.x + v3.x;
        acc.y += v0.y + v1.y + v2.y + v3.y;
        acc.z += v0.z + v1.z + v2.z + v3.z;
        acc.w += v0.w + v1.w + v2.w + v3.w;
    }
    for (; i < e; i++) {
        int nb = __ldg(&adj[i]);
        float4 v = *reinterpret_cast<const float4*>(&feat[(size_t)nb * HDIM + lane * 4]);
        acc.x += v.x; acc.y += v.y; acc.z += v.z; acc.w += v.w;
    }
    float inv = (e > s) ? 1.f / (float)(e - s) : 0.f;
    acc.x = f2tf32(acc.x * inv); acc.y = f2tf32(acc.y * inv);
    acc.z = f2tf32(acc.z * inv); acc.w = f2tf32(acc.w * inv);
    *reinterpret_cast<float4*>(&out[(size_t)w * HDIM + lane * 4]) = acc;
}

// ---------------- decoder (permutation-invariant over columns) ----------------
__global__ void decoder_kernel(const float* __restrict__ zu, const float* __restrict__ zr,
                               const int* __restrict__ ls, const int* __restrict__ ld,
                               float* __restrict__ out, int L) {
    int w = (blockIdx.x * blockDim.x + threadIdx.x) >> 5;
    if (w >= L) return;
    int lane = threadIdx.x & 31;
    int s = __ldg(&ls[w]), d = __ldg(&ld[w]);
    float2 a = *reinterpret_cast<const float2*>(&zu[(size_t)s * OUTDIM + lane * 2]);
    float2 b = *reinterpret_cast<const float2*>(&zr[(size_t)d * OUTDIM + lane * 2]);
    float dot = a.x * b.x + a.y * b.y;
    float na = a.x * a.x + a.y * a.y;
    float nb = b.x * b.x + b.y * b.y;
    #pragma unroll
    for (int o = 16; o > 0; o >>= 1) {
        dot += __shfl_xor_sync(0xffffffffu, dot, o);
        na  += __shfl_xor_sync(0xffffffffu, na, o);
        nb  += __shfl_xor_sync(0xffffffffu, nb, o);
    }
    if (lane == 0)
        out[w] = dot / (fmaxf(sqrtf(na), 1e-12f) * fmaxf(sqrtf(nb), 1e-12f));
}

// ---------------- launch ----------------
extern "C" void kernel_launch(void* const* d_in, const int* in_sizes, int n_in,
                              void* d_out, int out_size) {
    const float* x_user   = (const float*)d_in[0];
    const float* x_recipe = (const float*)d_in[1];
    const int* edge_src = (const int*)d_in[2];
    const int* edge_dst = (const int*)d_in[3];
    const int* lbl_src  = (const int*)d_in[4];
    const int* lbl_dst  = (const int*)d_in[5];
    const float* Wu   = (const float*)d_in[6];
    const float* bu   = (const float*)d_in[7];
    const float* Wrec = (const float*)d_in[8];
    const float* brec = (const float*)d_in[9];
    const float* c1urWl = (const float*)d_in[10];
    const float* c1urbl = (const float*)d_in[11];
    const float* c1urWr = (const float*)d_in[12];
    const float* c1ruWl = (const float*)d_in[13];
    const float* c1rubl = (const float*)d_in[14];
    const float* c1ruWr = (const float*)d_in[15];
    const float* c2urWl = (const float*)d_in[16];
    const float* c2urbl = (const float*)d_in[17];
    const float* c2urWr = (const float*)d_in[18];
    const float* c2ruWl = (const float*)d_in[19];
    const float* c2rubl = (const float*)d_in[20];
    const float* c2ruWr = (const float*)d_in[21];
    float* out = (float*)d_out;

    float *hu, *hr, *mean_r, *mean_u, *r1, *u1, *mr2, *mu2, *zr, *zu;
    float *wts, *xup, *xrp;
    int *off_r, *off_u, *cur_r, *cur_u, *adj_r, *adj_u, *bs_r, *bs_u;
    cudaGetSymbolAddress((void**)&hu, g_hu);
    cudaGetSymbolAddress((void**)&hr, g_hr);
    cudaGetSymbolAddress((void**)&mean_r, g_mean_r);
    cudaGetSymbolAddress((void**)&mean_u, g_mean_u);
    cudaGetSymbolAddress((void**)&r1, g_r1);
    cudaGetSymbolAddress((void**)&u1, g_u1);
    cudaGetSymbolAddress((void**)&mr2, g_mr2);
    cudaGetSymbolAddress((void**)&mu2, g_mu2);
    cudaGetSymbolAddress((void**)&zr, g_zr);
    cudaGetSymbolAddress((void**)&zu, g_zu);
    cudaGetSymbolAddress((void**)&wts, g_wts);
    cudaGetSymbolAddress((void**)&xup, g_xu);
    cudaGetSymbolAddress((void**)&xrp, g_xr);
    cudaGetSymbolAddress((void**)&off_r, g_off_r);
    cudaGetSymbolAddress((void**)&off_u, g_off_u);
    cudaGetSymbolAddress((void**)&cur_r, g_cur_r);
    cudaGetSymbolAddress((void**)&cur_u, g_cur_u);
    cudaGetSymbolAddress((void**)&adj_r, g_adj_r);
    cudaGetSymbolAddress((void**)&adj_u, g_adj_u);
    cudaGetSymbolAddress((void**)&bs_r, g_bsum_r);
    cudaGetSymbolAddress((void**)&bs_u, g_bsum_u);

    // tf32+permuted weight views
    const float* tWu     = wts;
    const float* tWrec   = wts + 16384;
    const float* tc1urWl = wts + 49152;
    const float* tc1urWr = wts + 65536;
    const float* tc1ruWl = wts + 81920;
    const float* tc1ruWr = wts + 98304;
    const float* tc2urWl = wts + 114688;
    const float* tc2urWr = wts + 122880;
    const float* tc2ruWl = wts + 131072;
    const float* tc2ruWr = wts + 139264;

    const int SM_H = 2 * (128 * 36 + 128 * 36) * 4;  // 73728 B (J=128)
    const int SM_O = 2 * (128 * 36 + 64 * 36) * 4;   // 55296 B (J=64)
    cudaFuncSetAttribute(gemm_mma<128, false, true>,
                         cudaFuncAttributeMaxDynamicSharedMemorySize, SM_H);
    cudaFuncSetAttribute(gemm_mma<128, true, true>,
                         cudaFuncAttributeMaxDynamicSharedMemorySize, SM_H);
    cudaFuncSetAttribute(gemm_mma<64, false, false>,
                         cudaFuncAttributeMaxDynamicSharedMemorySize, SM_O);

    const int CH_U = (N_USERS + 1023) / 1024;    // 98
    const int CH_R = (N_RECIPES + 1023) / 1024;  // 49
    const int GB_U = (N_USERS + 127) / 128;      // 782
    const int GB_R = (N_RECIPES + 127) / 128;    // 391

    // GEMM side descriptors (all sources pre-rounded & permuted)
    GSide proj_r = { xrp, tWrec, xrp, tWrec, brec, hr, N_RECIPES, 256, 8, 8, 128 };
    GSide proj_u = { xup, tWu,   xup, tWu,   bu,   hu, N_USERS,   128, 4, 4, 128 };
    GSide c1_r = { mean_r, tc1urWl, hr, tc1urWr, c1urbl, r1, N_RECIPES, 128, 8, 4, 128 };
    GSide c1_u = { mean_u, tc1ruWl, hu, tc1ruWr, c1rubl, u1, N_USERS,   128, 8, 4, 128 };
    GSide c2_r = { mr2, tc2urWl, r1, tc2urWr, c2urbl, zr, N_RECIPES, 128, 8, 4, 64 };
    GSide c2_u = { mu2, tc2ruWl, u1, tc2ruWr, c2rubl, zu, N_USERS,   128, 8, 4, 64 };

    const int PREP_TOTAL = W_TOTAL + XU_ELEMS + XR_ELEMS;

    // #1 prep (weights + inputs: round + permute)
    prep_all<<<(PREP_TOTAL + 255) / 256, 256>>>(
        Wu, Wrec, c1urWl, c1urWr, c1ruWl, c1ruWr,
        c2urWl, c2urWr, c2ruWl, c2ruWr, x_user, x_recipe, wts, xup, xrp);

    // #2-#3 CSR front
    zero_int2<<<(N_USERS + N_RECIPES + 255) / 256, 256>>>(cur_u, N_USERS, cur_r, N_RECIPES);
    count_deg<<<(NE + 255) / 256, 256>>>(edge_src, edge_dst, cur_u, cur_r, NE);

    // #4 combined input projections (ncu target slot)
    gemm_mma<128, false, true><<<GB_R + GB_U, 256, SM_H>>>(proj_r, proj_u, GB_R);

    // CSR rest
    scan_chunks2<<<CH_U + CH_R, 1024>>>(cur_u, off_u, bs_u, N_USERS, CH_U,
                                        cur_r, off_r, bs_r, N_RECIPES);
    scan_bsums2<<<2, 32>>>(bs_u, CH_U, bs_r, CH_R);
    add_bsums2<<<CH_U + CH_R, 1024>>>(off_u, bs_u, N_USERS, CH_U,
                                      off_r, bs_r, N_RECIPES);
    copy_int2<<<(N_USERS + N_RECIPES + 255) / 256, 256>>>(cur_u, off_u, N_USERS,
                                                          cur_r, off_r, N_RECIPES);
    fill_adj<<<(NE + 255) / 256, 256>>>(edge_src, edge_dst, cur_u, cur_r, adj_u, adj_r, NE);

    // conv1
    aggregate_mean2<<<((N_RECIPES + N_USERS) * 32 + 255) / 256, 256>>>(
        hu, off_r, adj_r, mean_r, N_RECIPES,
        hr, off_u, adj_u, mean_u, N_USERS);
    gemm_mma<128, true, true><<<GB_R + GB_U, 256, SM_H>>>(c1_r, c1_u, GB_R);

    // conv2
    aggregate_mean2<<<((N_RECIPES + N_USERS) * 32 + 255) / 256, 256>>>(
        u1, off_r, adj_r, mr2, N_RECIPES,
        r1, off_u, adj_u, mu2, N_USERS);
    gemm_mma<64, false, false><<<GB_R + GB_U, 256, SM_O>>>(c2_r, c2_u, GB_R);

    // decoder
    decoder_kernel<<<(NL + 7) / 8, 256>>>(zu, zr, lbl_src, lbl_dst, out, NL);
}

// round 8
// speedup vs baseline: 1.3895x; 1.3895x over previous
#include <cuda_runtime.h>
#include <cuda_fp16.h>
#include <math.h>
#include <stdint.h>

#define N_USERS   100000
#define N_RECIPES 50000
#define NE        600000
#define NL        200000
#define HDIM      128
#define OUTDIM    64

// ---------------- scratch (no allocation allowed) ----------------
__device__ __align__(128) float g_hu[(size_t)N_USERS * HDIM];
__device__ __align__(128) float g_hr[(size_t)N_RECIPES * HDIM];
__device__ __align__(128) float g_mean_r[(size_t)N_RECIPES * HDIM];
__device__ __align__(128) float g_mean_u[(size_t)N_USERS * HDIM];
__device__ __align__(128) float g_r1[(size_t)N_RECIPES * HDIM];
__device__ __align__(128) float g_u1[(size_t)N_USERS * HDIM];
__device__ __align__(128) float g_mr2[(size_t)N_RECIPES * HDIM];
__device__ __align__(128) float g_mu2[(size_t)N_USERS * HDIM];
__device__ __align__(128) float g_zr[(size_t)N_RECIPES * OUTDIM];
__device__ __align__(128) float g_zu[(size_t)N_USERS * OUTDIM];

__device__ __align__(128) int g_off_r[N_RECIPES + 1];
__device__ __align__(128) int g_off_u[N_USERS + 1];
__device__ __align__(128) int g_cur_r[N_RECIPES];
__device__ __align__(128) int g_cur_u[N_USERS];
__device__ __align__(128) int g_adj_r[NE];
__device__ __align__(128) int g_adj_u[NE];
__device__ __align__(128) int g_bsum_r[64];
__device__ __align__(128) int g_bsum_u[128];

// pre-converted fp16 weights
#define W_TOTAL 147456
__device__ __align__(128) __half g_wts[W_TOTAL];

// ---------------- fp16 mma helpers ----------------
__device__ __forceinline__ void mma_fp16(float* d,
                                         uint32_t a0, uint32_t a1, uint32_t a2, uint32_t a3,
                                         uint32_t b0, uint32_t b1) {
    asm volatile(
        "mma.sync.aligned.m16n8k16.row.col.f32.f16.f16.f32 "
        "{%0,%1,%2,%3}, {%4,%5,%6,%7}, {%8,%9}, {%0,%1,%2,%3};"
        : "+f"(d[0]), "+f"(d[1]), "+f"(d[2]), "+f"(d[3])
        : "r"(a0), "r"(a1), "r"(a2), "r"(a3), "r"(b0), "r"(b1));
}

__device__ __forceinline__ void cp_async16(uint32_t smem_dst, const void* gsrc) {
    asm volatile("cp.async.ca.shared.global [%0], [%1], 16;"
                 :: "r"(smem_dst), "l"(gsrc) : "memory");
}

__device__ __forceinline__ uint32_t pack_h2(float x, float y) {
    __half2 h = __floats2half2_rn(x, y);
    return *reinterpret_cast<uint32_t*>(&h);
}

// ---------------- weight prep: fp32 -> fp16 ----------------
__global__ void prep_weights(const float* __restrict__ w0, const float* __restrict__ w1,
                             const float* __restrict__ w2, const float* __restrict__ w3,
                             const float* __restrict__ w4, const float* __restrict__ w5,
                             const float* __restrict__ w6, const float* __restrict__ w7,
                             const float* __restrict__ w8, const float* __restrict__ w9,
                             __half* __restrict__ wts) {
    int i = blockIdx.x * blockDim.x + threadIdx.x;
    const float* src; int off;
    if      (i <  16384) { src = w0; off = 0;      }
    else if (i <  49152) { src = w1; off = 16384;  }
    else if (i <  65536) { src = w2; off = 49152;  }
    else if (i <  81920) { src = w3; off = 65536;  }
    else if (i <  98304) { src = w4; off = 81920;  }
    else if (i < 114688) { src = w5; off = 98304;  }
    else if (i < 122880) { src = w6; off = 114688; }
    else if (i < 131072) { src = w7; off = 122880; }
    else if (i < 139264) { src = w8; off = 131072; }
    else if (i < W_TOTAL){ src = w9; off = 139264; }
    else return;
    wts[i] = __float2half_rn(src[i - off]);
}

// ---------------- fused two-sided fp16 tensor-core GEMM ----------------
// out[n, J] = A[n,*] @ WA^T (+ B @ WB^T) + bias (+relu)
// A/B fp32 in global (converted to fp16 at smem store); weights pre-halved.
// Block 256 thr, tile 128 x J. Warps 4(m) x 2(n), warp tile 32 x J/2.
// K chunked by 32 (= 2 fp16 mma k-steps), double-buffered smem.
struct GSide {
    const float *A; const __half *WA;
    const float *B; const __half *WB;
    const float *bias;
    float *out;
    int n, lda, ldwa, ldb, ldwb, nch, cha;
};

template <int J, bool RELU>
__global__ __launch_bounds__(256, 2)
void gemm_mma(GSide s0, GSide s1, int split) {
    constexpr int LW  = 20;              // b32 words per smem row (16 data + 4 pad)
    constexpr int NT  = J / 16;          // 8 (J=128) / 4 (J=64)
    constexpr int WCP = J / 64;          // cp.async16 iters for W tile

    extern __shared__ uint32_t sm[];
    uint32_t* AsB = sm;                  // [2][128][LW]
    uint32_t* WsB = sm + 2 * 128 * LW;   // [2][J][LW]

    const bool second = ((int)blockIdx.x >= split);
    const GSide s = second ? s1 : s0;
    const int row0 = (second ? (int)blockIdx.x - split : (int)blockIdx.x) * 128;

    const int tid  = threadIdx.x;
    const int lane = tid & 31;
    const int wid  = tid >> 5;
    const int wm   = wid & 3;
    const int wn   = wid >> 2;
    const int qr   = lane >> 2;
    const int qc   = lane & 3;

    float acc[2][NT][4];
    #pragma unroll
    for (int mt = 0; mt < 2; mt++)
        #pragma unroll
        for (int nt = 0; nt < NT; nt++)
            #pragma unroll
            for (int q = 0; q < 4; q++) acc[mt][nt][q] = 0.f;

    uint2 pa[4];

    auto fetchA = [&](int c) {
        const float* src = (c < s.cha) ? s.A : s.B;
        const int ld = (c < s.cha) ? s.lda : s.ldb;
        const int k0 = ((c < s.cha) ? c : c - s.cha) * 32;
        #pragma unroll
        for (int i = 0; i < 4; i++) {
            int lin = tid + i * 256;
            int r = lin >> 3, qk = lin & 7;
            int gr = row0 + r;
            float4 v = (gr < s.n)
                ? *reinterpret_cast<const float4*>(&src[(size_t)gr * ld + k0 + qk * 4])
                : make_float4(0.f, 0.f, 0.f, 0.f);
            pa[i] = make_uint2(pack_h2(v.x, v.y), pack_h2(v.z, v.w));
        }
    };

    auto storeA = [&](int b) {
        uint32_t* as = AsB + b * 128 * LW;
        #pragma unroll
        for (int i = 0; i < 4; i++) {
            int lin = tid + i * 256;
            int r = lin >> 3, qk = lin & 7;
            *reinterpret_cast<uint2*>(&as[r * LW + qk * 2]) = pa[i];
        }
    };

    auto issueW = [&](int c, int b) {
        const __half* w = (c < s.cha) ? s.WA : s.WB;
        const int ld = (c < s.cha) ? s.ldwa : s.ldwb;
        const int k0 = ((c < s.cha) ? c : c - s.cha) * 32;
        uint32_t wbase = (uint32_t)__cvta_generic_to_shared(WsB + b * J * LW);
        #pragma unroll
        for (int i = 0; i < WCP; i++) {
            int lin = tid + i * 256;
            int j = lin >> 2, qw = lin & 3;
            cp_async16(wbase + (uint32_t)(j * LW + qw * 4) * 4,
                       &w[(size_t)j * ld + k0 + qw * 8]);
        }
        asm volatile("cp.async.commit_group;" ::: "memory");
    };

    fetchA(0);
    issueW(0, 0);
    storeA(0);
    asm volatile("cp.async.wait_group 0;" ::: "memory");
    __syncthreads();

    const int nch = s.nch;
    for (int c = 0; c < nch; ++c) {
        const int b = c & 1;
        if (c + 1 < nch) {
            fetchA(c + 1);
            issueW(c + 1, b ^ 1);
        }

        const uint32_t* as = AsB + b * 128 * LW + (wm * 32) * LW;
        const uint32_t* ws = WsB + b * J * LW + (wn * NT * 8) * LW;

        #pragma unroll
        for (int ks = 0; ks < 2; ++ks) {     // two k=16 steps per 32-chunk
            const int kb = qc + ks * 8;
            uint32_t af[2][4];
            #pragma unroll
            for (int mt = 0; mt < 2; mt++) {
                const uint32_t* ap = as + (mt * 16 + qr) * LW + kb;
                af[mt][0] = ap[0];
                af[mt][1] = ap[8 * LW];
                af[mt][2] = ap[4];
                af[mt][3] = ap[8 * LW + 4];
            }
            uint32_t bf[NT][2];
            #pragma unroll
            for (int nt = 0; nt < NT; nt++) {
                const uint32_t* bp = ws + (nt * 8 + qr) * LW + kb;
                bf[nt][0] = bp[0];
                bf[nt][1] = bp[4];
            }
            #pragma unroll
            for (int mt = 0; mt < 2; mt++)
                #pragma unroll
                for (int nt = 0; nt < NT; nt++)
                    mma_fp16(acc[mt][nt],
                             af[mt][0], af[mt][1], af[mt][2], af[mt][3],
                             bf[nt][0], bf[nt][1]);
        }

        if (c + 1 < nch) {
            storeA(b ^ 1);
            asm volatile("cp.async.wait_group 0;" ::: "memory");
            __syncthreads();
        }
    }

    // epilogue: C frag (m16n8): {c0,c1} row=qr col=2qc; {c2,c3} row=qr+8
    #pragma unroll
    for (int mt = 0; mt < 2; mt++) {
        #pragma unroll
        for (int nt = 0; nt < NT; nt++) {
            int gcol = wn * NT * 8 + nt * 8 + 2 * qc;
            float bx = __ldg(&s.bias[gcol]), by = __ldg(&s.bias[gcol + 1]);
            int r0 = row0 + wm * 32 + mt * 16 + qr;
            float v0 = acc[mt][nt][0] + bx, v1 = acc[mt][nt][1] + by;
            float v2 = acc[mt][nt][2] + bx, v3 = acc[mt][nt][3] + by;
            if (RELU) {
                v0 = fmaxf(v0, 0.f); v1 = fmaxf(v1, 0.f);
                v2 = fmaxf(v2, 0.f); v3 = fmaxf(v3, 0.f);
            }
            if (r0 < s.n)
                *reinterpret_cast<float2*>(&s.out[(size_t)r0 * J + gcol]) = make_float2(v0, v1);
            if (r0 + 8 < s.n)
                *reinterpret_cast<float2*>(&s.out[(size_t)(r0 + 8) * J + gcol]) = make_float2(v2, v3);
        }
    }
}

// ---------------- merged small utility kernels ----------------
__global__ void zero_int2(int* __restrict__ p0, int n0, int* __restrict__ p1, int n1) {
    int i = blockIdx.x * blockDim.x + threadIdx.x;
    if (i < n0) p0[i] = 0;
    else if (i < n0 + n1) p1[i - n0] = 0;
}

__global__ void copy_int2(int* __restrict__ d0, const int* __restrict__ s0, int n0,
                          int* __restrict__ d1, const int* __restrict__ s1, int n1) {
    int i = blockIdx.x * blockDim.x + threadIdx.x;
    if (i < n0) d0[i] = s0[i];
    else if (i < n0 + n1) d1[i - n0] = s1[i - n0];
}

__global__ void count_deg(const int* __restrict__ es, const int* __restrict__ ed,
                          int* __restrict__ deg_u, int* __restrict__ deg_r, int E) {
    int e = blockIdx.x * blockDim.x + threadIdx.x;
    if (e < E) {
        atomicAdd(&deg_u[es[e]], 1);
        atomicAdd(&deg_r[ed[e]], 1);
    }
}

__global__ void scan_chunks2(const int* __restrict__ dg0, int* __restrict__ of0,
                             int* __restrict__ bs0, int n0, int nb0,
                             const int* __restrict__ dg1, int* __restrict__ of1,
                             int* __restrict__ bs1, int n1) {
    const int* deg; int* off; int* bsum; int n, lb;
    if ((int)blockIdx.x < nb0) { deg = dg0; off = of0; bsum = bs0; n = n0; lb = blockIdx.x; }
    else { deg = dg1; off = of1; bsum = bs1; n = n1; lb = blockIdx.x - nb0; }
    __shared__ int sh[1024];
    int t = threadIdx.x;
    int gid = lb * 1024 + t;
    int v = (gid < n) ? deg[gid] : 0;
    sh[t] = v;
    __syncthreads();
    #pragma unroll
    for (int d = 1; d < 1024; d <<= 1) {
        int add = (t >= d) ? sh[t - d] : 0;
        __syncthreads();
        sh[t] += add;
        __syncthreads();
    }
    if (gid < n) off[gid + 1] = sh[t];
    if (t == 1023) bsum[lb] = sh[1023];
    if (gid == 0) off[0] = 0;
}

__global__ void scan_bsums2(int* __restrict__ b0, int nb0, int* __restrict__ b1, int nb1) {
    if (threadIdx.x != 0) return;
    int* b = (blockIdx.x == 0) ? b0 : b1;
    int nb = (blockIdx.x == 0) ? nb0 : nb1;
    int acc = 0;
    for (int i = 0; i < nb; i++) { int t = b[i]; b[i] = acc; acc += t; }
}

__global__ void add_bsums2(int* __restrict__ of0, const int* __restrict__ bs0, int n0, int nb0,
                           int* __restrict__ of1, const int* __restrict__ bs1, int n1) {
    int* off; const int* bsum; int n, lb;
    if ((int)blockIdx.x < nb0) { off = of0; bsum = bs0; n = n0; lb = blockIdx.x; }
    else { off = of1; bsum = bs1; n = n1; lb = blockIdx.x - nb0; }
    int gid = lb * 1024 + threadIdx.x;
    if (gid < n) off[gid + 1] += bsum[lb];
}

__global__ void fill_adj(const int* __restrict__ es, const int* __restrict__ ed,
                         int* __restrict__ cur_u, int* __restrict__ cur_r,
                         int* __restrict__ adj_u, int* __restrict__ adj_r, int E) {
    int e = blockIdx.x * blockDim.x + threadIdx.x;
    if (e < E) {
        int s = es[e], d = ed[e];
        adj_r[atomicAdd(&cur_r[d], 1)] = s;
        adj_u[atomicAdd(&cur_u[s], 1)] = d;
    }
}

// ---------------- merged scatter-mean, 4-way unrolled gather ----------------
__global__ void aggregate_mean2(
    const float* __restrict__ f0, const int* __restrict__ o0,
    const int* __restrict__ a0, float* __restrict__ out0, int n0,
    const float* __restrict__ f1, const int* __restrict__ o1,
    const int* __restrict__ a1, float* __restrict__ out1, int n1) {
    int w = (blockIdx.x * blockDim.x + threadIdx.x) >> 5;
    const float* feat; const int* off; const int* adj; float* out;
    if (w < n0) { feat = f0; off = o0; adj = a0; out = out0; }
    else {
        w -= n0;
        if (w >= n1) return;
        feat = f1; off = o1; adj = a1; out = out1;
    }
    int lane = threadIdx.x & 31;
    int s = off[w], e = off[w + 1];
    float4 acc = make_float4(0.f, 0.f, 0.f, 0.f);
    int i = s;
    for (; i + 4 <= e; i += 4) {
        int nb0 = __ldg(&adj[i]);
        int nb1 = __ldg(&adj[i + 1]);
        int nb2 = __ldg(&adj[i + 2]);
        int nb3 = __ldg(&adj[i + 3]);
        float4 v0 = *reinterpret_cast<const float4*>(&feat[(size_t)nb0 * HDIM + lane * 4]);
        float4 v1 = *reinterpret_cast<const float4*>(&feat[(size_t)nb1 * HDIM + lane * 4]);
        float4 v2 = *reinterpret_cast<const float4*>(&feat[(size_t)nb2 * HDIM + lane * 4]);
        float4 v3 = *reinterpret_cast<const float4*>(&feat[(size_t)nb3 * HDIM + lane * 4]);
        acc.x += v0.x + v1.x + v2.x + v3.x;
        acc.y += v0.y + v1.y + v2.y + v3.y;
        acc.z += v0.z + v1.z + v2.z + v3.z;
        acc.w += v0.w + v1.w + v2.w + v3.w;
    }
    for (; i < e; i++) {
        int nb = __ldg(&adj[i]);
        float4 v = *reinterpret_cast<const float4*>(&feat[(size_t)nb * HDIM + lane * 4]);
        acc.x += v.x; acc.y += v.y; acc.z += v.z; acc.w += v.w;
    }
    float inv = (e > s) ? 1.f / (float)(e - s) : 0.f;
    acc.x *= inv; acc.y *= inv; acc.z *= inv; acc.w *= inv;
    *reinterpret_cast<float4*>(&out[(size_t)w * HDIM + lane * 4]) = acc;
}

// ---------------- decoder ----------------
__global__ void decoder_kernel(const float* __restrict__ zu, const float* __restrict__ zr,
                               const int* __restrict__ ls, const int* __restrict__ ld,
                               float* __restrict__ out, int L) {
    int w = (blockIdx.x * blockDim.x + threadIdx.x) >> 5;
    if (w >= L) return;
    int lane = threadIdx.x & 31;
    int s = __ldg(&ls[w]), d = __ldg(&ld[w]);
    float2 a = *reinterpret_cast<const float2*>(&zu[(size_t)s * OUTDIM + lane * 2]);
    float2 b = *reinterpret_cast<const float2*>(&zr[(size_t)d * OUTDIM + lane * 2]);
    float dot = a.x * b.x + a.y * b.y;
    float na = a.x * a.x + a.y * a.y;
    float nb = b.x * b.x + b.y * b.y;
    #pragma unroll
    for (int o = 16; o > 0; o >>= 1) {
        dot += __shfl_xor_sync(0xffffffffu, dot, o);
        na  += __shfl_xor_sync(0xffffffffu, na, o);
        nb  += __shfl_xor_sync(0xffffffffu, nb, o);
    }
    if (lane == 0)
        out[w] = dot / (fmaxf(sqrtf(na), 1e-12f) * fmaxf(sqrtf(nb), 1e-12f));
}

// ---------------- launch ----------------
extern "C" void kernel_launch(void* const* d_in, const int* in_sizes, int n_in,
                              void* d_out, int out_size) {
    const float* x_user   = (const float*)d_in[0];
    const float* x_recipe = (const float*)d_in[1];
    const int* edge_src = (const int*)d_in[2];
    const int* edge_dst = (const int*)d_in[3];
    const int* lbl_src  = (const int*)d_in[4];
    const int* lbl_dst  = (const int*)d_in[5];
    const float* Wu   = (const float*)d_in[6];
    const float* bu   = (const float*)d_in[7];
    const float* Wrec = (const float*)d_in[8];
    const float* brec = (const float*)d_in[9];
    const float* c1urWl = (const float*)d_in[10];
    const float* c1urbl = (const float*)d_in[11];
    const float* c1urWr = (const float*)d_in[12];
    const float* c1ruWl = (const float*)d_in[13];
    const float* c1rubl = (const float*)d_in[14];
    const float* c1ruWr = (const float*)d_in[15];
    const float* c2urWl = (const float*)d_in[16];
    const float* c2urbl = (const float*)d_in[17];
    const float* c2urWr = (const float*)d_in[18];
    const float* c2ruWl = (const float*)d_in[19];
    const float* c2rubl = (const float*)d_in[20];
    const float* c2ruWr = (const float*)d_in[21];
    float* out = (float*)d_out;

    float *hu, *hr, *mean_r, *mean_u, *r1, *u1, *mr2, *mu2, *zr, *zu;
    __half* wts;
    int *off_r, *off_u, *cur_r, *cur_u, *adj_r, *adj_u, *bs_r, *bs_u;
    cudaGetSymbolAddress((void**)&hu, g_hu);
    cudaGetSymbolAddress((void**)&hr, g_hr);
    cudaGetSymbolAddress((void**)&mean_r, g_mean_r);
    cudaGetSymbolAddress((void**)&mean_u, g_mean_u);
    cudaGetSymbolAddress((void**)&r1, g_r1);
    cudaGetSymbolAddress((void**)&u1, g_u1);
    cudaGetSymbolAddress((void**)&mr2, g_mr2);
    cudaGetSymbolAddress((void**)&mu2, g_mu2);
    cudaGetSymbolAddress((void**)&zr, g_zr);
    cudaGetSymbolAddress((void**)&zu, g_zu);
    cudaGetSymbolAddress((void**)&wts, g_wts);
    cudaGetSymbolAddress((void**)&off_r, g_off_r);
    cudaGetSymbolAddress((void**)&off_u, g_off_u);
    cudaGetSymbolAddress((void**)&cur_r, g_cur_r);
    cudaGetSymbolAddress((void**)&cur_u, g_cur_u);
    cudaGetSymbolAddress((void**)&adj_r, g_adj_r);
    cudaGetSymbolAddress((void**)&adj_u, g_adj_u);
    cudaGetSymbolAddress((void**)&bs_r, g_bsum_r);
    cudaGetSymbolAddress((void**)&bs_u, g_bsum_u);

    // fp16 weight views
    const __half* tWu     = wts;
    const __half* tWrec   = wts + 16384;
    const __half* tc1urWl = wts + 49152;
    const __half* tc1urWr = wts + 65536;
    const __half* tc1ruWl = wts + 81920;
    const __half* tc1ruWr = wts + 98304;
    const __half* tc2urWl = wts + 114688;
    const __half* tc2urWr = wts + 122880;
    const __half* tc2ruWl = wts + 131072;
    const __half* tc2ruWr = wts + 139264;

    // dynamic smem: (2 stages A 128x20 + 2 stages W Jx20) b32 words
    const int SM_H = (2 * 128 * 20 + 2 * 128 * 20) * 4;  // 40960 B (J=128)
    const int SM_O = (2 * 128 * 20 + 2 * 64 * 20) * 4;   // 30720 B (J=64)
    cudaFuncSetAttribute(gemm_mma<128, false>,
                         cudaFuncAttributeMaxDynamicSharedMemorySize, SM_H);
    cudaFuncSetAttribute(gemm_mma<128, true>,
                         cudaFuncAttributeMaxDynamicSharedMemorySize, SM_H);
    cudaFuncSetAttribute(gemm_mma<64, false>,
                         cudaFuncAttributeMaxDynamicSharedMemorySize, SM_O);

    const int CH_U = (N_USERS + 1023) / 1024;    // 98
    const int CH_R = (N_RECIPES + 1023) / 1024;  // 49
    const int GB_U = (N_USERS + 127) / 128;      // 782
    const int GB_R = (N_RECIPES + 127) / 128;    // 391

    // GEMM side descriptors
    GSide proj_r = { x_recipe, tWrec, x_recipe + 128, tWrec + 128, brec, hr,
                     N_RECIPES, 256, 256, 256, 256, 8, 4 };
    GSide proj_u = { x_user, tWu, x_user, tWu, bu, hu,
                     N_USERS, 128, 128, 128, 128, 4, 4 };
    GSide c1_r = { mean_r, tc1urWl, hr, tc1urWr, c1urbl, r1,
                   N_RECIPES, 128, 128, 128, 128, 8, 4 };
    GSide c1_u = { mean_u, tc1ruWl, hu, tc1ruWr, c1rubl, u1,
                   N_USERS, 128, 128, 128, 128, 8, 4 };
    GSide c2_r = { mr2, tc2urWl, r1, tc2urWr, c2urbl, zr,
                   N_RECIPES, 128, 128, 128, 128, 8, 4 };
    GSide c2_u = { mu2, tc2ruWl, u1, tc2ruWr, c2rubl, zu,
                   N_USERS, 128, 128, 128, 128, 8, 4 };

    // #1 weight prep (tiny)
    prep_weights<<<(W_TOTAL + 255) / 256, 256>>>(
        Wu, Wrec, c1urWl, c1urWr, c1ruWl, c1ruWr,
        c2urWl, c2urWr, c2ruWl, c2ruWr, wts);

    // #2-#3 CSR front
    zero_int2<<<(N_USERS + N_RECIPES + 255) / 256, 256>>>(cur_u, N_USERS, cur_r, N_RECIPES);
    count_deg<<<(NE + 255) / 256, 256>>>(edge_src, edge_dst, cur_u, cur_r, NE);

    // #4 combined input projections (ncu target slot)
    gemm_mma<128, false><<<GB_R + GB_U, 256, SM_H>>>(proj_r, proj_u, GB_R);

    // CSR rest
    scan_chunks2<<<CH_U + CH_R, 1024>>>(cur_u, off_u, bs_u, N_USERS, CH_U,
                                        cur_r, off_r, bs_r, N_RECIPES);
    scan_bsums2<<<2, 32>>>(bs_u, CH_U, bs_r, CH_R);
    add_bsums2<<<CH_U + CH_R, 1024>>>(off_u, bs_u, N_USERS, CH_U,
                                      off_r, bs_r, N_RECIPES);
    copy_int2<<<(N_USERS + N_RECIPES + 255) / 256, 256>>>(cur_u, off_u, N_USERS,
                                                          cur_r, off_r, N_RECIPES);
    fill_adj<<<(NE + 255) / 256, 256>>>(edge_src, edge_dst, cur_u, cur_r, adj_u, adj_r, NE);

    // conv1
    aggregate_mean2<<<((N_RECIPES + N_USERS) * 32 + 255) / 256, 256>>>(
        hu, off_r, adj_r, mean_r, N_RECIPES,
        hr, off_u, adj_u, mean_u, N_USERS);
    gemm_mma<128, true><<<GB_R + GB_U, 256, SM_H>>>(c1_r, c1_u, GB_R);

    // conv2
    aggregate_mean2<<<((N_RECIPES + N_USERS) * 32 + 255) / 256, 256>>>(
        u1, off_r, adj_r, mr2, N_RECIPES,
        r1, off_u, adj_u, mu2, N_USERS);
    gemm_mma<64, false><<<GB_R + GB_U, 256, SM_O>>>(c2_r, c2_u, GB_R);

    // decoder
    decoder_kernel<<<(NL + 7) / 8, 256>>>(zu, zr, lbl_src, lbl_dst, out, NL);
}